// round 4
// baseline (speedup 1.0000x reference)
#include <cuda_runtime.h>
#include <cstdint>

#define BATCH 8192
#define DCONT 1024
#define VCAT  10000
#define VEC   2500          // float4s per categorical row
#define FULL  0xffffffffu

// Gathering lane accumulates one full W_cat row (64B, L2-resident) locally.
__device__ __forceinline__ void addrow(const float4* __restrict__ Wcat4,
                                       int col, float* a, int& cnt) {
    cnt++;
    const float4* w = Wcat4 + (size_t)col * 4;
    #pragma unroll
    for (int q = 0; q < 4; q++) {
        float4 t = __ldg(w + q);
        a[4*q+0] += t.x; a[4*q+1] += t.y; a[4*q+2] += t.z; a[4*q+3] += t.w;
    }
}

// Ballot-free vector processing: integer zero test, rare divergent gather.
#define PROC(v, idx)                                                        \
    do {                                                                    \
        if (((v).x | (v).y | (v).z | (v).w) != 0u) {                        \
            int col = (idx) * 4;                                            \
            if ((v).x) addrow(Wcat4, col + 0, a, cnt);                      \
            if ((v).y) addrow(Wcat4, col + 1, a, cnt);                      \
            if ((v).z) addrow(Wcat4, col + 2, a, cnt);                      \
            if ((v).w) addrow(Wcat4, col + 3, a, cnt);                      \
        }                                                                   \
    } while (0)

__global__ void __launch_bounds__(128, 8)
spfl_kernel(const float* __restrict__ xcont,
            const float* __restrict__ xcat,
            const float* __restrict__ Wc,
            const float* __restrict__ Wcat,
            const float* __restrict__ bias,
            float* __restrict__ out) {
    const int warp = (blockIdx.x * blockDim.x + threadIdx.x) >> 5;
    const int lane = threadIdx.x & 31;
    if (warp >= BATCH) return;
    const int row = warp;
    const int g = lane >> 2;

    const uint4*  __restrict__ xr    = reinterpret_cast<const uint4*>(xcat) + (size_t)row * VEC;
    const float4* __restrict__ Wcat4 = reinterpret_cast<const float4*>(Wcat);
    const float4* __restrict__ Wc4   = reinterpret_cast<const float4*>(Wc);

    // ---- cat phase: per-lane 16-float accumulator, no warp convergence ops ----
    float a[16];
    #pragma unroll
    for (int k = 0; k < 16; k++) a[k] = 0.f;
    int cnt = 0;

    // main: 19 iterations x 128 vectors (batch of 4 per lane), covers 2432
    #pragma unroll 1
    for (int it = 0; it < 19; it++) {
        int base = it * 128 + lane;
        uint4 v0 = __ldg(xr + base);
        uint4 v1 = __ldg(xr + base + 32);
        uint4 v2 = __ldg(xr + base + 64);
        uint4 v3 = __ldg(xr + base + 96);
        PROC(v0, base);
        PROC(v1, base + 32);
        PROC(v2, base + 64);
        PROC(v3, base + 96);
    }
    // tail: vectors [2432, 2500)
    {
        uint4 z = make_uint4(0u, 0u, 0u, 0u);
        int b0 = 2432 + lane;
        uint4 t0 = (b0      < VEC) ? __ldg(xr + b0)      : z;
        uint4 t1 = (b0 + 32 < VEC) ? __ldg(xr + b0 + 32) : z;
        uint4 t2 = (b0 + 64 < VEC) ? __ldg(xr + b0 + 64) : z;
        PROC(t0, b0);
        PROC(t1, b0 + 32);
        PROC(t2, b0 + 64);
    }

    // ---- phase boundary: butterfly-reduce 16 floats + cnt across the warp ----
    #pragma unroll
    for (int off = 16; off >= 1; off >>= 1) {
        #pragma unroll
        for (int k = 0; k < 16; k++) a[k] += __shfl_xor_sync(FULL, a[k], off);
        cnt += __shfl_xor_sync(FULL, cnt, off);
    }
    // lanes 0-3 seed the c/g-layout accumulator with their output quarter
    float4 acc = make_float4(0.f, 0.f, 0.f, 0.f);
    if      (lane == 0) acc = make_float4(a[0],  a[1],  a[2],  a[3]);
    else if (lane == 1) acc = make_float4(a[4],  a[5],  a[6],  a[7]);
    else if (lane == 2) acc = make_float4(a[8],  a[9],  a[10], a[11]);
    else if (lane == 3) acc = make_float4(a[12], a[13], a[14], a[15]);

    // ---- cont phase: c/g layout, each warp LDG.128 covers 512B contiguous ----
    const float* __restrict__ xc = xcont + (size_t)row * DCONT;
    const int c = lane & 3;
    for (int jb = 0; jb < DCONT; jb += 32) {
        float x = __ldg(xc + jb + lane);
        #pragma unroll
        for (int s = 0; s < 4; s++) {
            int jl = s * 8 + g;
            float4 w = __ldg(Wc4 + (size_t)(jb + jl) * 4 + c);
            float xv = __shfl_sync(FULL, x, jl);
            acc.x += xv * w.x; acc.y += xv * w.y;
            acc.z += xv * w.z; acc.w += xv * w.w;
        }
    }

    // ---- reduce cont partials over g (cat part rides along in g==0 lanes) ----
    #pragma unroll
    for (int off = 4; off <= 16; off <<= 1) {
        acc.x += __shfl_xor_sync(FULL, acc.x, off);
        acc.y += __shfl_xor_sync(FULL, acc.y, off);
        acc.z += __shfl_xor_sync(FULL, acc.z, off);
        acc.w += __shfl_xor_sync(FULL, acc.w, off);
    }

    if (lane < 4) {   // g == 0, quarter c == lane; cnt already warp-complete
        float4 b4 = __ldg(reinterpret_cast<const float4*>(bias) + lane);
        float f = (float)(DCONT + cnt);
        acc.x += f * b4.x; acc.y += f * b4.y;
        acc.z += f * b4.z; acc.w += f * b4.w;
        reinterpret_cast<float4*>(out)[(size_t)row * 4 + lane] = acc;
    }
}

extern "C" void kernel_launch(void* const* d_in, const int* in_sizes, int n_in,
                              void* d_out, int out_size) {
    const float* xcont = (const float*)d_in[0];   // [8192, 1024]
    const float* xcat  = (const float*)d_in[1];   // [8192, 10000]
    const float* Wc    = (const float*)d_in[2];   // [1024, 16]
    const float* Wcat  = (const float*)d_in[3];   // [10000, 16]
    const float* bias  = (const float*)d_in[4];   // [16]
    float* out = (float*)d_out;                   // [8192, 16]

    // 1 row per warp, 4 warps per block -> 2048 blocks
    dim3 grid(BATCH / 4);
    dim3 block(128);
    spfl_kernel<<<grid, block>>>(xcont, xcat, Wc, Wcat, bias, out);
}

// round 5
// speedup vs baseline: 1.3018x; 1.3018x over previous
#include <cuda_runtime.h>
#include <cstdint>

#define BATCH 8192
#define DCONT 1024
#define VCAT  10000
#define VEC   2500          // float4s per categorical row
#define FULL  0xffffffffu

// Process one 128-vector chunk position j for one row.
// All lanes load the gathered W row (broadcast across the 8 g-groups, 64B
// span -> 2 sectors), add is predicated on g==0. No divergent branches.
__device__ __forceinline__ void proc_vec(uint4 v, int vbase,
                                         const float4* __restrict__ Wcat4,
                                         float4& acc, int& cnt,
                                         int g, int c) {
    unsigned m4 = (v.x ? 1u : 0u) | (v.y ? 2u : 0u)
                | (v.z ? 4u : 0u) | (v.w ? 8u : 0u);
    cnt += __popc(m4);
    unsigned bal = __ballot_sync(FULL, m4 != 0u);
    while (bal) {
        int src = __ffs(bal) - 1;
        bal &= bal - 1;
        unsigned sm4 = __shfl_sync(FULL, m4, src);
        int scol = (vbase + src) * 4;   // vocab column of source lane's v.x
        if (sm4 & 1u) { float4 w = __ldg(Wcat4 + (size_t)(scol + 0) * 4 + c);
            if (g == 0) { acc.x += w.x; acc.y += w.y; acc.z += w.z; acc.w += w.w; } }
        if (sm4 & 2u) { float4 w = __ldg(Wcat4 + (size_t)(scol + 1) * 4 + c);
            if (g == 0) { acc.x += w.x; acc.y += w.y; acc.z += w.z; acc.w += w.w; } }
        if (sm4 & 4u) { float4 w = __ldg(Wcat4 + (size_t)(scol + 2) * 4 + c);
            if (g == 0) { acc.x += w.x; acc.y += w.y; acc.z += w.z; acc.w += w.w; } }
        if (sm4 & 8u) { float4 w = __ldg(Wcat4 + (size_t)(scol + 3) * 4 + c);
            if (g == 0) { acc.x += w.x; acc.y += w.y; acc.z += w.z; acc.w += w.w; } }
    }
}

__global__ void __launch_bounds__(128)
spfl_kernel(const float* __restrict__ xcont,
            const float* __restrict__ xcat,
            const float* __restrict__ Wc,
            const float* __restrict__ Wcat,
            const float* __restrict__ bias,
            float* __restrict__ out) {
    const int warp = (blockIdx.x * blockDim.x + threadIdx.x) >> 5;
    const int lane = threadIdx.x & 31;
    const int g = lane >> 2;
    const int c = lane & 3;

    const int row0 = warp * 2;
    if (row0 >= BATCH) return;
    const int row1 = row0 + 1;

    const uint4*  __restrict__ xr0   = reinterpret_cast<const uint4*>(xcat) + (size_t)row0 * VEC;
    const uint4*  __restrict__ xr1   = reinterpret_cast<const uint4*>(xcat) + (size_t)row1 * VEC;
    const float4* __restrict__ Wcat4 = reinterpret_cast<const float4*>(Wcat);
    const float4* __restrict__ Wc4   = reinterpret_cast<const float4*>(Wc);

    float4 acc0 = make_float4(0.f, 0.f, 0.f, 0.f);
    float4 acc1 = make_float4(0.f, 0.f, 0.f, 0.f);
    int cnt0 = 0, cnt1 = 0;

    // ---- categorical: interleave both rows' streams, 8 LDG.128 in flight ----
    const uint4 z = make_uint4(0u, 0u, 0u, 0u);
    #pragma unroll 1
    for (int i0 = 0; i0 < VEC; i0 += 128) {
        uint4 va[4], vb[4];
        #pragma unroll
        for (int j = 0; j < 4; j++) {
            int idx = i0 + j * 32 + lane;
            va[j] = (idx < VEC) ? __ldg(xr0 + idx) : z;
        }
        #pragma unroll
        for (int j = 0; j < 4; j++) {
            int idx = i0 + j * 32 + lane;
            vb[j] = (idx < VEC) ? __ldg(xr1 + idx) : z;
        }
        #pragma unroll
        for (int j = 0; j < 4; j++)
            proc_vec(va[j], i0 + j * 32, Wcat4, acc0, cnt0, g, c);
        #pragma unroll
        for (int j = 0; j < 4; j++)
            proc_vec(vb[j], i0 + j * 32, Wcat4, acc1, cnt1, g, c);
    }

    // ---- continuous: c/g layout, warp LDG.128 covers 512B contiguous ----
    const float* __restrict__ xc0 = xcont + (size_t)row0 * DCONT;
    const float* __restrict__ xc1 = xcont + (size_t)row1 * DCONT;
    #pragma unroll 1
    for (int jb = 0; jb < DCONT; jb += 32) {
        float x0 = __ldg(xc0 + jb + lane);
        float x1 = __ldg(xc1 + jb + lane);
        #pragma unroll
        for (int s = 0; s < 4; s++) {
            int jl = s * 8 + g;
            float4 w = __ldg(Wc4 + (size_t)(jb + jl) * 4 + c);
            float a0 = __shfl_sync(FULL, x0, jl);
            float a1 = __shfl_sync(FULL, x1, jl);
            acc0.x += a0 * w.x; acc0.y += a0 * w.y; acc0.z += a0 * w.z; acc0.w += a0 * w.w;
            acc1.x += a1 * w.x; acc1.y += a1 * w.y; acc1.z += a1 * w.z; acc1.w += a1 * w.w;
        }
    }

    // ---- reduce acc over g (offsets 4,8,16); cnt over all lanes ----
    #pragma unroll
    for (int off = 4; off <= 16; off <<= 1) {
        acc0.x += __shfl_xor_sync(FULL, acc0.x, off);
        acc0.y += __shfl_xor_sync(FULL, acc0.y, off);
        acc0.z += __shfl_xor_sync(FULL, acc0.z, off);
        acc0.w += __shfl_xor_sync(FULL, acc0.w, off);
        acc1.x += __shfl_xor_sync(FULL, acc1.x, off);
        acc1.y += __shfl_xor_sync(FULL, acc1.y, off);
        acc1.z += __shfl_xor_sync(FULL, acc1.z, off);
        acc1.w += __shfl_xor_sync(FULL, acc1.w, off);
    }
    #pragma unroll
    for (int off = 1; off <= 16; off <<= 1) {
        cnt0 += __shfl_xor_sync(FULL, cnt0, off);
        cnt1 += __shfl_xor_sync(FULL, cnt1, off);
    }

    if (lane < 4) {   // g == 0, quarter c == lane
        float4 b4 = __ldg(reinterpret_cast<const float4*>(bias) + lane);
        float f0 = (float)(DCONT + cnt0);
        float f1 = (float)(DCONT + cnt1);
        float4 o0, o1;
        o0.x = acc0.x + f0 * b4.x; o0.y = acc0.y + f0 * b4.y;
        o0.z = acc0.z + f0 * b4.z; o0.w = acc0.w + f0 * b4.w;
        o1.x = acc1.x + f1 * b4.x; o1.y = acc1.y + f1 * b4.y;
        o1.z = acc1.z + f1 * b4.z; o1.w = acc1.w + f1 * b4.w;
        reinterpret_cast<float4*>(out)[(size_t)row0 * 4 + lane] = o0;
        reinterpret_cast<float4*>(out)[(size_t)row1 * 4 + lane] = o1;
    }
}

extern "C" void kernel_launch(void* const* d_in, const int* in_sizes, int n_in,
                              void* d_out, int out_size) {
    const float* xcont = (const float*)d_in[0];   // [8192, 1024]
    const float* xcat  = (const float*)d_in[1];   // [8192, 10000]
    const float* Wc    = (const float*)d_in[2];   // [1024, 16]
    const float* Wcat  = (const float*)d_in[3];   // [10000, 16]
    const float* bias  = (const float*)d_in[4];   // [16]
    float* out = (float*)d_out;                   // [8192, 16]

    // 2 rows per warp, 4 warps per block -> 1024 blocks (single wave)
    dim3 grid(BATCH / 8);
    dim3 block(128);
    spfl_kernel<<<grid, block>>>(xcont, xcat, Wc, Wcat, bias, out);
}

// round 6
// speedup vs baseline: 1.3542x; 1.0403x over previous
#include <cuda_runtime.h>
#include <cstdint>

#define BATCH 8192
#define DCONT 1024
#define VCAT  10000
#define VEC   2500          // float4s per categorical row
#define FULL  0xffffffffu

__device__ __forceinline__ float u2f(unsigned u) { return __uint_as_float(u); }

// Gather-add W_cat row `col` (broadcast load across warp, add predicated g==0)
#define WADD(col)                                                            \
    do { float4 w = __ldg(Wcat4 + (size_t)(col) * 4 + c);                    \
         if (g == 0) { acc.x += w.x; acc.y += w.y;                           \
                       acc.z += w.z; acc.w += w.w; } } while (0)

// Process one chunk (2 vectors per lane) for one row: 1 ballot, float count.
__device__ __forceinline__ void proc2(uint4 v0, uint4 v1, int vbase,
                                      const float4* __restrict__ Wcat4,
                                      float4& acc, float& fcnt,
                                      int g, int c) {
    fcnt += ((u2f(v0.x) + u2f(v0.y)) + (u2f(v0.z) + u2f(v0.w)))
          + ((u2f(v1.x) + u2f(v1.y)) + (u2f(v1.z) + u2f(v1.w)));
    unsigned nz = (v0.x | v0.y | v0.z | v0.w) | (v1.x | v1.y | v1.z | v1.w);
    unsigned bal = __ballot_sync(FULL, nz != 0u);
    while (bal) {                         // rare: ~0.5 sources per chunk
        int src = __ffs(bal) - 1;
        bal &= bal - 1;
        unsigned s0x = __shfl_sync(FULL, v0.x, src);
        unsigned s0y = __shfl_sync(FULL, v0.y, src);
        unsigned s0z = __shfl_sync(FULL, v0.z, src);
        unsigned s0w = __shfl_sync(FULL, v0.w, src);
        unsigned s1x = __shfl_sync(FULL, v1.x, src);
        unsigned s1y = __shfl_sync(FULL, v1.y, src);
        unsigned s1z = __shfl_sync(FULL, v1.z, src);
        unsigned s1w = __shfl_sync(FULL, v1.w, src);
        int col0 = (vbase + src) * 4;
        int col1 = (vbase + 32 + src) * 4;
        if (s0x) WADD(col0 + 0);
        if (s0y) WADD(col0 + 1);
        if (s0z) WADD(col0 + 2);
        if (s0w) WADD(col0 + 3);
        if (s1x) WADD(col1 + 0);
        if (s1y) WADD(col1 + 1);
        if (s1z) WADD(col1 + 2);
        if (s1w) WADD(col1 + 3);
    }
}

__global__ void __launch_bounds__(128, 8)
spfl_kernel(const float* __restrict__ xcont,
            const float* __restrict__ xcat,
            const float* __restrict__ Wc,
            const float* __restrict__ Wcat,
            const float* __restrict__ bias,
            float* __restrict__ out) {
    const int warp = (blockIdx.x * blockDim.x + threadIdx.x) >> 5;
    const int lane = threadIdx.x & 31;
    const int g = lane >> 2;
    const int c = lane & 3;

    const int row0 = warp * 2;
    if (row0 >= BATCH) return;

    const uint4*  __restrict__ xr0   = reinterpret_cast<const uint4*>(xcat) + (size_t)row0 * VEC;
    const uint4*  __restrict__ xr1   = xr0 + VEC;
    const float4* __restrict__ Wcat4 = reinterpret_cast<const float4*>(Wcat);
    const float4* __restrict__ Wc4   = reinterpret_cast<const float4*>(Wc);

    float4 acc;  // row0 partial (c-quarter, g-split)
    float4 acc1_v;
    acc    = make_float4(0.f, 0.f, 0.f, 0.f);
    acc1_v = make_float4(0.f, 0.f, 0.f, 0.f);
    float fcnt0 = 0.f, fcnt1 = 0.f;

    const uint4 z = make_uint4(0u, 0u, 0u, 0u);

    // ---- categorical: prefetch-pipelined stream, 1 ballot per 64 vectors/row ----
    // chunk = 64 vectors per row (lane holds idx base+lane and base+32+lane)
    uint4 a0, a1, b0, b1;                 // current chunk (row0: a*, row1: b*)
    {
        int i0 = lane, i1 = lane + 32;    // chunk 0 is fully in range
        a0 = __ldg(xr0 + i0); a1 = __ldg(xr0 + i1);
        b0 = __ldg(xr1 + i0); b1 = __ldg(xr1 + i1);
    }
    #pragma unroll 1
    for (int base = 0; base < 2560; base += 64) {   // 40 chunks covers 2500
        int nb = base + 64;
        uint4 na0 = z, na1 = z, nb0 = z, nb1 = z;
        if (nb < 2560) {                  // prefetch next chunk (guarded tail)
            int i0 = nb + lane, i1 = nb + lane + 32;
            na0 = (i0 < VEC) ? __ldg(xr0 + i0) : z;
            na1 = (i1 < VEC) ? __ldg(xr0 + i1) : z;
            nb0 = (i0 < VEC) ? __ldg(xr1 + i0) : z;
            nb1 = (i1 < VEC) ? __ldg(xr1 + i1) : z;
        }
        proc2(a0, a1, base, Wcat4, acc,    fcnt0, g, c);
        proc2(b0, b1, base, Wcat4, acc1_v, fcnt1, g, c);
        a0 = na0; a1 = na1; b0 = nb0; b1 = nb1;
    }

    // ---- continuous: c/g layout, warp LDG.128 covers 512B contiguous ----
    const float* __restrict__ xc0 = xcont + (size_t)row0 * DCONT;
    const float* __restrict__ xc1 = xc0 + DCONT;
    #pragma unroll 1
    for (int jb = 0; jb < DCONT; jb += 32) {
        float x0 = __ldg(xc0 + jb + lane);
        float x1 = __ldg(xc1 + jb + lane);
        #pragma unroll
        for (int s = 0; s < 4; s++) {
            int jl = s * 8 + g;
            float4 w = __ldg(Wc4 + (size_t)(jb + jl) * 4 + c);
            float v0 = __shfl_sync(FULL, x0, jl);
            float v1 = __shfl_sync(FULL, x1, jl);
            acc.x    += v0 * w.x; acc.y    += v0 * w.y;
            acc.z    += v0 * w.z; acc.w    += v0 * w.w;
            acc1_v.x += v1 * w.x; acc1_v.y += v1 * w.y;
            acc1_v.z += v1 * w.z; acc1_v.w += v1 * w.w;
        }
    }

    // ---- reduce acc over g (offsets 4,8,16); counts over all lanes ----
    #pragma unroll
    for (int off = 4; off <= 16; off <<= 1) {
        acc.x    += __shfl_xor_sync(FULL, acc.x, off);
        acc.y    += __shfl_xor_sync(FULL, acc.y, off);
        acc.z    += __shfl_xor_sync(FULL, acc.z, off);
        acc.w    += __shfl_xor_sync(FULL, acc.w, off);
        acc1_v.x += __shfl_xor_sync(FULL, acc1_v.x, off);
        acc1_v.y += __shfl_xor_sync(FULL, acc1_v.y, off);
        acc1_v.z += __shfl_xor_sync(FULL, acc1_v.z, off);
        acc1_v.w += __shfl_xor_sync(FULL, acc1_v.w, off);
    }
    #pragma unroll
    for (int off = 1; off <= 16; off <<= 1) {
        fcnt0 += __shfl_xor_sync(FULL, fcnt0, off);
        fcnt1 += __shfl_xor_sync(FULL, fcnt1, off);
    }

    if (lane < 4) {   // g == 0, quarter c == lane
        float4 b4 = __ldg(reinterpret_cast<const float4*>(bias) + lane);
        float f0 = (float)DCONT + fcnt0;
        float f1 = (float)DCONT + fcnt1;
        float4 o0, o1;
        o0.x = acc.x    + f0 * b4.x; o0.y = acc.y    + f0 * b4.y;
        o0.z = acc.z    + f0 * b4.z; o0.w = acc.w    + f0 * b4.w;
        o1.x = acc1_v.x + f1 * b4.x; o1.y = acc1_v.y + f1 * b4.y;
        o1.z = acc1_v.z + f1 * b4.z; o1.w = acc1_v.w + f1 * b4.w;
        reinterpret_cast<float4*>(out)[(size_t)row0 * 4 + lane]       = o0;
        reinterpret_cast<float4*>(out)[(size_t)(row0 + 1) * 4 + lane] = o1;
    }
}

extern "C" void kernel_launch(void* const* d_in, const int* in_sizes, int n_in,
                              void* d_out, int out_size) {
    const float* xcont = (const float*)d_in[0];   // [8192, 1024]
    const float* xcat  = (const float*)d_in[1];   // [8192, 10000]
    const float* Wc    = (const float*)d_in[2];   // [1024, 16]
    const float* Wcat  = (const float*)d_in[3];   // [10000, 16]
    const float* bias  = (const float*)d_in[4];   // [16]
    float* out = (float*)d_out;                   // [8192, 16]

    // 2 rows per warp, 4 warps per block -> 1024 blocks
    dim3 grid(BATCH / 8);
    dim3 block(128);
    spfl_kernel<<<grid, block>>>(xcont, xcat, Wc, Wcat, bias, out);
}